// round 8
// baseline (speedup 1.0000x reference)
#include <cuda_runtime.h>

#define LAT 64
#define QB 128
#define OSPLIT 37
#define CHUNK 56          // ceil(2048/37)
#define MAXN 4096
#define CELLS 64          // 4x4x4 spatial bins

// scratch (static device arrays; no allocation allowed)
__device__ float4 g_aq[MAXN * (LAT / 4)];
__device__ float4 g_bo[MAXN * (LAT / 4)];
__device__ float4 g_v [MAXN * (LAT / 4)];
__device__ float  g_pnum[(size_t)OSPLIT * LAT * MAXN];
__device__ float  g_pden[OSPLIT * MAXN];
__device__ int    g_key[MAXN];
__device__ int    g_order[MAXN];

__device__ __forceinline__ unsigned long long pk2(float a, float b) {
    unsigned long long r;
    asm("mov.b64 %0, {%1, %2};" : "=l"(r) : "f"(a), "f"(b));
    return r;
}
__device__ __forceinline__ void upk2(unsigned long long v, float& a, float& b) {
    asm("mov.b64 {%0, %1}, %2;" : "=f"(a), "=f"(b) : "l"(v));
}
__device__ __forceinline__ unsigned long long ffma2(unsigned long long a,
                                                    unsigned long long b,
                                                    unsigned long long c) {
    unsigned long long d;
    asm("fma.rn.f32x2 %0, %1, %2, %3;" : "=l"(d) : "l"(a), "l"(b), "l"(c));
    return d;
}
__device__ __forceinline__ unsigned long long fadd2(unsigned long long a,
                                                    unsigned long long b) {
    unsigned long long d;
    asm("add.rn.f32x2 %0, %1, %2;" : "=l"(d) : "l"(a), "l"(b));
    return d;
}

// ---------------------------------------------------------------------------
// prep: 16 rows per 256-thread block; thread t -> (row = t/16, 4 l's = (t%16)*4)
// Computes aq[q,:], bo[o,:], v[o,:] = h_obs@Wv+bv, and spatial cell key per q.
// ---------------------------------------------------------------------------
__global__ __launch_bounds__(256) void prep_kernel(
        const float* __restrict__ h_obs,
        const float* __restrict__ pos_obs,
        const float* __restrict__ pos_query,
        const float* __restrict__ W1,
        const float* __restrict__ b1,
        const float* __restrict__ Wv,
        const float* __restrict__ bv,
        int N_q, int N_o) {
    __shared__ float4 wv_s[LAT * 16];   // 64 x 64 floats = 16KB
    __shared__ float  hs[16 * LAT];     // 16 rows of h_obs

    const int t  = threadIdx.x;
    const int r0 = blockIdx.x * 16;
    const int rl = t >> 4;
    const int lg = t & 15;

    const float4* Wv4 = (const float4*)Wv;
    #pragma unroll
    for (int i = 0; i < 4; ++i) wv_s[t + i * 256] = Wv4[t + i * 256];

    if (r0 < N_o) {
        int nrow = N_o - r0; if (nrow > 16) nrow = 16;
        const float4* h4 = (const float4*)h_obs;
        for (int i = t; i < nrow * 16; i += 256)
            ((float4*)hs)[i] = h4[r0 * 16 + i];
    }
    __syncthreads();

    const int row = r0 + rl;
    const float4* W14 = (const float4*)W1;

    if (row < N_o) {
        // v = h_obs @ Wv + bv (4 columns per thread)
        float4 bvv = ((const float4*)bv)[lg];
        float ax = bvv.x, ay = bvv.y, az = bvv.z, aw = bvv.w;
        #pragma unroll 8
        for (int k = 0; k < LAT; ++k) {
            float h  = hs[rl * LAT + k];
            float4 w = wv_s[k * 16 + lg];
            ax = fmaf(h, w.x, ax); ay = fmaf(h, w.y, ay);
            az = fmaf(h, w.z, az); aw = fmaf(h, w.w, aw);
        }
        g_v[row * 16 + lg] = make_float4(ax, ay, az, aw);

        float px = pos_obs[row * 3 + 0];
        float py = pos_obs[row * 3 + 1];
        float pz = pos_obs[row * 3 + 2];
        float4 w3 = W14[3 * 16 + lg], w4 = W14[4 * 16 + lg], w5 = W14[5 * 16 + lg];
        float4 w6 = W14[6 * 16 + lg], w7 = W14[7 * 16 + lg], w8 = W14[8 * 16 + lg];
        float4 bb = ((const float4*)b1)[lg];
        float4 r;
        r.x = bb.x + px * (w3.x - w6.x) + py * (w4.x - w7.x) + pz * (w5.x - w8.x);
        r.y = bb.y + px * (w3.y - w6.y) + py * (w4.y - w7.y) + pz * (w5.y - w8.y);
        r.z = bb.z + px * (w3.z - w6.z) + py * (w4.z - w7.z) + pz * (w5.z - w8.z);
        r.w = bb.w + px * (w3.w - w6.w) + py * (w4.w - w7.w) + pz * (w5.w - w8.w);
        g_bo[row * 16 + lg] = r;
    }

    if (row < N_q) {
        float px = pos_query[row * 3 + 0];
        float py = pos_query[row * 3 + 1];
        float pz = pos_query[row * 3 + 2];
        float4 w0 = W14[0 * 16 + lg], w1 = W14[1 * 16 + lg], w2 = W14[2 * 16 + lg];
        float4 w6 = W14[6 * 16 + lg], w7 = W14[7 * 16 + lg], w8 = W14[8 * 16 + lg];
        float4 a;
        a.x = px * (w0.x + w6.x) + py * (w1.x + w7.x) + pz * (w2.x + w8.x);
        a.y = px * (w0.y + w6.y) + py * (w1.y + w7.y) + pz * (w2.y + w8.y);
        a.z = px * (w0.z + w6.z) + py * (w1.z + w7.z) + pz * (w2.z + w8.z);
        a.w = px * (w0.w + w6.w) + py * (w1.w + w7.w) + pz * (w2.w + w8.w);
        g_aq[row * 16 + lg] = a;

        if (lg == 0) {
            int cx = (int)(px * 4.f); cx = cx < 0 ? 0 : (cx > 3 ? 3 : cx);
            int cy = (int)(py * 4.f); cy = cy < 0 ? 0 : (cy > 3 ? 3 : cy);
            int cz = (int)(pz * 4.f); cz = cz < 0 ? 0 : (cz > 3 ? 3 : cz);
            g_key[row] = (cz * 4 + cy) * 4 + cx;
        }
    }
}

// ---------------------------------------------------------------------------
// sort: single block. hist -> scan -> scatter. Order within a bin is
// nondeterministic but query math is position-independent -> output bitwise
// deterministic.
// ---------------------------------------------------------------------------
__global__ __launch_bounds__(1024) void sort_kernel(int N_q) {
    __shared__ int hist[CELLS];
    __shared__ int offs[CELLS];
    int t = threadIdx.x;
    if (t < CELLS) hist[t] = 0;
    __syncthreads();
    for (int i = t; i < N_q; i += 1024) atomicAdd(&hist[g_key[i]], 1);
    __syncthreads();
    if (t == 0) {
        int run = 0;
        for (int b = 0; b < CELLS; ++b) { offs[b] = run; run += hist[b]; }
    }
    __syncthreads();
    for (int i = t; i < N_q; i += 1024) {
        int pos = atomicAdd(&offs[g_key[i]], 1);
        g_order[pos] = i;
    }
}

// ---------------------------------------------------------------------------
// main: thread = one sorted query p; blockIdx.y = o-split (37 chunks of <=56).
// Warp-uniform radius culling via __any_sync (queries spatially sorted).
// ---------------------------------------------------------------------------
__global__ __launch_bounds__(QB, 2) void main_kernel(
        const float* __restrict__ pos_query,
        const float* __restrict__ pos_obs,
        const float* __restrict__ W2,
        int N_q, int N_o) {
    __shared__ ulonglong2 bo_s[CHUNK * 16];
    __shared__ ulonglong2 v_s [CHUNK * 16];
    __shared__ float4 pos_s[CHUNK];
    __shared__ unsigned long long w2s[LAT / 2];

    const int tid = threadIdx.x;
    const int o0  = blockIdx.y * CHUNK;
    int oCount = N_o - o0;
    if (oCount > CHUNK) oCount = CHUNK;
    if (oCount < 0) oCount = 0;

    const ulonglong2* gb = (const ulonglong2*)g_bo;
    const ulonglong2* gv = (const ulonglong2*)g_v;
    for (int i = tid; i < oCount * 16; i += QB) {
        bo_s[i] = gb[o0 * 16 + i];
        v_s[i]  = gv[o0 * 16 + i];
    }
    if (tid < oCount) {
        int o = o0 + tid;
        pos_s[tid] = make_float4(pos_obs[o * 3 + 0], pos_obs[o * 3 + 1],
                                 pos_obs[o * 3 + 2], 0.f);
    }
    if (tid < LAT / 2) w2s[tid] = pk2(W2[2 * tid], W2[2 * tid + 1]);
    __syncthreads();

    const int p = blockIdx.x * QB + tid;
    const int q = (p < N_q) ? g_order[p] : g_order[0];

    unsigned long long aq2[LAT / 2];
    const ulonglong2* ga = (const ulonglong2*)g_aq;
    #pragma unroll
    for (int j = 0; j < 16; ++j) {
        ulonglong2 u = ga[q * 16 + j];
        aq2[2 * j + 0] = u.x;
        aq2[2 * j + 1] = u.y;
    }
    const float qx = pos_query[q * 3 + 0];
    const float qy = pos_query[q * 3 + 1];
    const float qz = pos_query[q * 3 + 2];

    unsigned long long acc[LAT / 2];
    #pragma unroll
    for (int j = 0; j < LAT / 2; ++j) acc[j] = 0ull;
    float den = 0.f;

    for (int o = 0; o < oCount; ++o) {
        float4 P = pos_s[o];
        float dx = qx - P.x, dy = qy - P.y, dz = qz - P.z;
        float d2 = fmaf(dx, dx, fmaf(dy, dy, dz * dz));
        bool pass = (d2 <= 0.25f);
        if (!__any_sync(0xFFFFFFFFu, pass)) continue;

        const ulonglong2* bo = &bo_s[o * 16];
        unsigned long long l0 = 0, l1 = 0, l2 = 0, l3 = 0;
        #pragma unroll
        for (int j = 0; j < 16; ++j) {
            ulonglong2 b = bo[j];
            unsigned long long s0 = fadd2(aq2[2 * j + 0], b.x);
            unsigned long long s1 = fadd2(aq2[2 * j + 1], b.y);
            float h0, h1, h2, h3;
            upk2(s0, h0, h1);
            upk2(s1, h2, h3);
            h0 = fmaxf(h0, 0.f); h1 = fmaxf(h1, 0.f);
            h2 = fmaxf(h2, 0.f); h3 = fmaxf(h3, 0.f);
            if (j & 1) {
                l2 = ffma2(pk2(h0, h1), w2s[2 * j + 0], l2);
                l3 = ffma2(pk2(h2, h3), w2s[2 * j + 1], l3);
            } else {
                l0 = ffma2(pk2(h0, h1), w2s[2 * j + 0], l0);
                l1 = ffma2(pk2(h2, h3), w2s[2 * j + 1], l1);
            }
        }
        unsigned long long ls = fadd2(fadd2(l0, l1), fadd2(l2, l3));
        float xa, xb;
        upk2(ls, xa, xb);
        float logit = xa + xb;

        float e = pass ? __expf(logit) : 0.f;
        den += e;

        unsigned long long e2 = pk2(e, e);
        const ulonglong2* vv = &v_s[o * 16];
        #pragma unroll
        for (int j = 0; j < 16; ++j) {
            ulonglong2 V = vv[j];
            acc[2 * j + 0] = ffma2(e2, V.x, acc[2 * j + 0]);
            acc[2 * j + 1] = ffma2(e2, V.y, acc[2 * j + 1]);
        }
    }

    if (p < N_q) {
        const int s = blockIdx.y;
        #pragma unroll
        for (int j = 0; j < LAT / 2; ++j) {
            float a, b;
            upk2(acc[j], a, b);
            g_pnum[(size_t)(s * LAT + 2 * j + 0) * N_q + p] = a;  // coalesced over p
            g_pnum[(size_t)(s * LAT + 2 * j + 1) * N_q + p] = b;
        }
        g_pden[s * N_q + p] = den;
    }
}

// ---------------------------------------------------------------------------
// combine: sum partials over 37 splits, normalize, scatter to original q.
// ---------------------------------------------------------------------------
__global__ void combine_kernel(float* __restrict__ out, int N_q) {
    int t = blockIdx.x * blockDim.x + threadIdx.x;
    if (t >= N_q * LAT) return;
    int l = t / N_q;
    int p = t - l * N_q;
    float num = 0.f, den = 0.f;
    #pragma unroll
    for (int s = 0; s < OSPLIT; ++s) {
        num += g_pnum[(size_t)(s * LAT + l) * N_q + p];
        den += g_pden[s * N_q + p];
    }
    int q = g_order[p];
    out[q * LAT + l] = num / den;
}

extern "C" void kernel_launch(void* const* d_in, const int* in_sizes, int n_in,
                              void* d_out, int out_size) {
    const float* h_obs     = (const float*)d_in[0];
    // d_in[1] = x_obs: unused by the reference computation
    const float* pos_obs   = (const float*)d_in[2];
    const float* pos_query = (const float*)d_in[3];
    const float* W1        = (const float*)d_in[4];
    const float* b1        = (const float*)d_in[5];
    const float* W2        = (const float*)d_in[6];
    // d_in[7] = b2: uniform logit shift, cancels in softmax
    const float* Wv        = (const float*)d_in[8];
    const float* bv        = (const float*)d_in[9];

    const int N_o = in_sizes[0] / LAT;
    const int N_q = in_sizes[3] / 3;
    float* out = (float*)d_out;

    int R = (N_q > N_o) ? N_q : N_o;
    prep_kernel<<<(R + 15) / 16, 256>>>(h_obs, pos_obs, pos_query, W1, b1, Wv,
                                        bv, N_q, N_o);
    sort_kernel<<<1, 1024>>>(N_q);

    dim3 grid((N_q + QB - 1) / QB, OSPLIT);
    main_kernel<<<grid, QB>>>(pos_query, pos_obs, W2, N_q, N_o);

    int tot = N_q * LAT;
    combine_kernel<<<(tot + 255) / 256, 256>>>(out, N_q);
}

// round 9
// speedup vs baseline: 1.4239x; 1.4239x over previous
#include <cuda_runtime.h>

#define LAT 64
#define QB 128
#define OSPLIT 18
#define MAXN 4096

// scratch (static device arrays; no allocation allowed)
__device__ float4 g_aq[MAXN * (LAT / 4)];
__device__ float4 g_bo[MAXN * (LAT / 4)];
__device__ float4 g_v [MAXN * (LAT / 4)];
__device__ float  g_pnum[(size_t)OSPLIT * LAT * MAXN];
__device__ float  g_pden[OSPLIT * MAXN];

__device__ __forceinline__ unsigned long long pk2(float a, float b) {
    unsigned long long r;
    asm("mov.b64 %0, {%1, %2};" : "=l"(r) : "f"(a), "f"(b));
    return r;
}
__device__ __forceinline__ void upk2(unsigned long long v, float& a, float& b) {
    asm("mov.b64 {%0, %1}, %2;" : "=f"(a), "=f"(b) : "l"(v));
}
__device__ __forceinline__ unsigned long long ffma2(unsigned long long a,
                                                    unsigned long long b,
                                                    unsigned long long c) {
    unsigned long long d;
    asm("fma.rn.f32x2 %0, %1, %2, %3;" : "=l"(d) : "l"(a), "l"(b), "l"(c));
    return d;
}
__device__ __forceinline__ unsigned long long fadd2(unsigned long long a,
                                                    unsigned long long b) {
    unsigned long long d;
    asm("add.rn.f32x2 %0, %1, %2;" : "=l"(d) : "l"(a), "l"(b));
    return d;
}

// ---------------------------------------------------------------------------
// prep: 16 rows per 256-thread block; thread t -> (row = t/16, 4 l's = (t%16)*4)
// Computes aq[q,:], bo[o,:], v[o,:] = h_obs@Wv+bv.
// ---------------------------------------------------------------------------
__global__ __launch_bounds__(256) void prep_kernel(
        const float* __restrict__ h_obs,
        const float* __restrict__ pos_obs,
        const float* __restrict__ pos_query,
        const float* __restrict__ W1,
        const float* __restrict__ b1,
        const float* __restrict__ Wv,
        const float* __restrict__ bv,
        int N_q, int N_o) {
    __shared__ float4 wv_s[LAT * 16];   // 64 x 64 floats = 16KB
    __shared__ float  hs[16 * LAT];     // 16 rows of h_obs

    const int t  = threadIdx.x;
    const int r0 = blockIdx.x * 16;
    const int rl = t >> 4;
    const int lg = t & 15;

    const float4* Wv4 = (const float4*)Wv;
    #pragma unroll
    for (int i = 0; i < 4; ++i) wv_s[t + i * 256] = Wv4[t + i * 256];

    if (r0 < N_o) {
        int nrow = N_o - r0; if (nrow > 16) nrow = 16;
        const float4* h4 = (const float4*)h_obs;
        for (int i = t; i < nrow * 16; i += 256)
            ((float4*)hs)[i] = h4[r0 * 16 + i];
    }
    __syncthreads();

    const int row = r0 + rl;
    const float4* W14 = (const float4*)W1;

    if (row < N_o) {
        // v = h_obs @ Wv + bv (4 columns per thread)
        float4 bvv = ((const float4*)bv)[lg];
        float ax = bvv.x, ay = bvv.y, az = bvv.z, aw = bvv.w;
        #pragma unroll 8
        for (int k = 0; k < LAT; ++k) {
            float h  = hs[rl * LAT + k];
            float4 w = wv_s[k * 16 + lg];
            ax = fmaf(h, w.x, ax); ay = fmaf(h, w.y, ay);
            az = fmaf(h, w.z, az); aw = fmaf(h, w.w, aw);
        }
        g_v[row * 16 + lg] = make_float4(ax, ay, az, aw);

        float px = pos_obs[row * 3 + 0];
        float py = pos_obs[row * 3 + 1];
        float pz = pos_obs[row * 3 + 2];
        float4 w3 = W14[3 * 16 + lg], w4 = W14[4 * 16 + lg], w5 = W14[5 * 16 + lg];
        float4 w6 = W14[6 * 16 + lg], w7 = W14[7 * 16 + lg], w8 = W14[8 * 16 + lg];
        float4 bb = ((const float4*)b1)[lg];
        float4 r;
        r.x = bb.x + px * (w3.x - w6.x) + py * (w4.x - w7.x) + pz * (w5.x - w8.x);
        r.y = bb.y + px * (w3.y - w6.y) + py * (w4.y - w7.y) + pz * (w5.y - w8.y);
        r.z = bb.z + px * (w3.z - w6.z) + py * (w4.z - w7.z) + pz * (w5.z - w8.z);
        r.w = bb.w + px * (w3.w - w6.w) + py * (w4.w - w7.w) + pz * (w5.w - w8.w);
        g_bo[row * 16 + lg] = r;
    }

    if (row < N_q) {
        float px = pos_query[row * 3 + 0];
        float py = pos_query[row * 3 + 1];
        float pz = pos_query[row * 3 + 2];
        float4 w0 = W14[0 * 16 + lg], w1 = W14[1 * 16 + lg], w2 = W14[2 * 16 + lg];
        float4 w6 = W14[6 * 16 + lg], w7 = W14[7 * 16 + lg], w8 = W14[8 * 16 + lg];
        float4 a;
        a.x = px * (w0.x + w6.x) + py * (w1.x + w7.x) + pz * (w2.x + w8.x);
        a.y = px * (w0.y + w6.y) + py * (w1.y + w7.y) + pz * (w2.y + w8.y);
        a.z = px * (w0.z + w6.z) + py * (w1.z + w7.z) + pz * (w2.z + w8.z);
        a.w = px * (w0.w + w6.w) + py * (w1.w + w7.w) + pz * (w2.w + w8.w);
        g_aq[row * 16 + lg] = a;
    }
}

// ---------------------------------------------------------------------------
// main (round-6 structure): thread-per-query, o split OSPLIT ways across
// blockIdx.y; chunk large (dynamic smem). Unnormalized exp partials written
// coalesced as [s][l][q].
// ---------------------------------------------------------------------------
__global__ __launch_bounds__(QB, 2) void main_kernel(
        const float* __restrict__ pos_query,
        const float* __restrict__ pos_obs,
        const float* __restrict__ W2,
        int N_q, int N_o, int chunk) {
    extern __shared__ char smem_raw[];
    float4* bo_s  = (float4*)smem_raw;                 // chunk * 16
    float4* v_s   = bo_s + (size_t)chunk * 16;         // chunk * 16
    float4* pos_s = v_s + (size_t)chunk * 16;          // chunk
    unsigned long long* w2s = (unsigned long long*)(pos_s + chunk);  // LAT/2

    const int tid = threadIdx.x;
    const int o0  = blockIdx.y * chunk;
    int oCount = N_o - o0;
    if (oCount > chunk) oCount = chunk;
    if (oCount < 0) oCount = 0;

    const int nv = oCount * (LAT / 4);
    for (int i = tid; i < nv; i += QB) {
        bo_s[i] = g_bo[o0 * (LAT / 4) + i];
        v_s[i]  = g_v [o0 * (LAT / 4) + i];
    }
    for (int i = tid; i < oCount; i += QB) {
        int o = o0 + i;
        pos_s[i] = make_float4(pos_obs[o * 3 + 0], pos_obs[o * 3 + 1],
                               pos_obs[o * 3 + 2], 0.f);
    }
    if (tid < LAT / 2) w2s[tid] = pk2(W2[2 * tid], W2[2 * tid + 1]);
    __syncthreads();

    int q = blockIdx.x * QB + tid;
    if (q >= N_q) return;

    float aq[LAT];
    #pragma unroll
    for (int j = 0; j < LAT / 4; ++j) {
        float4 t = g_aq[q * (LAT / 4) + j];
        aq[4 * j + 0] = t.x; aq[4 * j + 1] = t.y;
        aq[4 * j + 2] = t.z; aq[4 * j + 3] = t.w;
    }
    const float qx = pos_query[q * 3 + 0];
    const float qy = pos_query[q * 3 + 1];
    const float qz = pos_query[q * 3 + 2];

    unsigned long long acc[LAT / 2];
    #pragma unroll
    for (int j = 0; j < LAT / 2; ++j) acc[j] = 0ull;
    float den = 0.f;

    for (int o = 0; o < oCount; ++o) {
        float4 p = pos_s[o];
        float dx = qx - p.x, dy = qy - p.y, dz = qz - p.z;
        float d2 = fmaf(dx, dx, fmaf(dy, dy, dz * dz));

        const float4* bo4 = &bo_s[o * (LAT / 4)];
        unsigned long long l0 = 0, l1 = 0, l2 = 0, l3 = 0;
        #pragma unroll
        for (int j = 0; j < LAT / 4; ++j) {
            float4 b = bo4[j];
            float h0 = fmaxf(aq[4 * j + 0] + b.x, 0.f);
            float h1 = fmaxf(aq[4 * j + 1] + b.y, 0.f);
            float h2 = fmaxf(aq[4 * j + 2] + b.z, 0.f);
            float h3 = fmaxf(aq[4 * j + 3] + b.w, 0.f);
            if (j & 1) {
                l2 = ffma2(pk2(h0, h1), w2s[2 * j + 0], l2);
                l3 = ffma2(pk2(h2, h3), w2s[2 * j + 1], l3);
            } else {
                l0 = ffma2(pk2(h0, h1), w2s[2 * j + 0], l0);
                l1 = ffma2(pk2(h2, h3), w2s[2 * j + 1], l1);
            }
        }
        unsigned long long ls = fadd2(fadd2(l0, l1), fadd2(l2, l3));
        float xa, xb;
        upk2(ls, xa, xb);
        float logit = xa + xb;

        // radius mask; unnormalized exp (logits are O(1), no overflow risk)
        float e = (d2 <= 0.25f) ? __expf(logit) : 0.f;
        den += e;

        unsigned long long e2 = pk2(e, e);
        const float4* v4 = &v_s[o * (LAT / 4)];
        #pragma unroll
        for (int j = 0; j < LAT / 4; ++j) {
            float4 vv = v4[j];
            acc[2 * j + 0] = ffma2(e2, pk2(vv.x, vv.y), acc[2 * j + 0]);
            acc[2 * j + 1] = ffma2(e2, pk2(vv.z, vv.w), acc[2 * j + 1]);
        }
    }

    const int s = blockIdx.y;
    #pragma unroll
    for (int j = 0; j < LAT / 2; ++j) {
        float a, b;
        upk2(acc[j], a, b);
        g_pnum[(size_t)(s * LAT + 2 * j + 0) * N_q + q] = a;  // coalesced over q
        g_pnum[(size_t)(s * LAT + 2 * j + 1) * N_q + q] = b;
    }
    g_pden[s * N_q + q] = den;
}

// ---------------------------------------------------------------------------
// combine: each thread sums OSPLIT partials for 4 l's of one query (90
// independent coalesced loads, fully unrolled -> high MLP), normalizes, and
// stores one float4.
// ---------------------------------------------------------------------------
__global__ __launch_bounds__(256) void combine_kernel(float* __restrict__ out,
                                                      int N_q) {
    int t = blockIdx.x * blockDim.x + threadIdx.x;
    int total = (LAT / 4) * N_q;
    if (t >= total) return;
    int l4 = t / N_q;
    int q  = t - l4 * N_q;

    float n0 = 0.f, n1 = 0.f, n2 = 0.f, n3 = 0.f, den = 0.f;
    #pragma unroll
    for (int s = 0; s < OSPLIT; ++s) {
        size_t base = (size_t)(s * LAT + 4 * l4) * N_q + q;
        n0 += g_pnum[base];
        n1 += g_pnum[base + (size_t)N_q];
        n2 += g_pnum[base + (size_t)2 * N_q];
        n3 += g_pnum[base + (size_t)3 * N_q];
        den += g_pden[s * N_q + q];
    }
    float inv = 1.f / den;
    ((float4*)out)[q * (LAT / 4) + l4] =
        make_float4(n0 * inv, n1 * inv, n2 * inv, n3 * inv);
}

extern "C" void kernel_launch(void* const* d_in, const int* in_sizes, int n_in,
                              void* d_out, int out_size) {
    const float* h_obs     = (const float*)d_in[0];
    // d_in[1] = x_obs: unused by the reference computation
    const float* pos_obs   = (const float*)d_in[2];
    const float* pos_query = (const float*)d_in[3];
    const float* W1        = (const float*)d_in[4];
    const float* b1        = (const float*)d_in[5];
    const float* W2        = (const float*)d_in[6];
    // d_in[7] = b2: uniform logit shift, cancels in softmax
    const float* Wv        = (const float*)d_in[8];
    const float* bv        = (const float*)d_in[9];

    const int N_o = in_sizes[0] / LAT;
    const int N_q = in_sizes[3] / 3;
    float* out = (float*)d_out;

    int R = (N_q > N_o) ? N_q : N_o;
    prep_kernel<<<(R + 15) / 16, 256>>>(h_obs, pos_obs, pos_query, W1, b1, Wv,
                                        bv, N_q, N_o);

    const int chunk = (N_o + OSPLIT - 1) / OSPLIT;   // 114 for N_o=2048
    size_t smem = (size_t)chunk * 16 * sizeof(float4) * 2   // bo_s + v_s
                + (size_t)chunk * sizeof(float4)            // pos_s
                + (LAT / 2) * sizeof(unsigned long long);   // w2s
    static int smem_set = 0;
    if (!smem_set) {
        cudaFuncSetAttribute(main_kernel,
                             cudaFuncAttributeMaxDynamicSharedMemorySize,
                             (int)smem);
        smem_set = 1;
    }
    dim3 grid((N_q + QB - 1) / QB, OSPLIT);
    main_kernel<<<grid, QB, smem>>>(pos_query, pos_obs, W2, N_q, N_o, chunk);

    int tot = (LAT / 4) * N_q;
    combine_kernel<<<(tot + 255) / 256, 256>>>(out, N_q);
}